// round 3
// baseline (speedup 1.0000x reference)
#include <cuda_runtime.h>

// LWTA: groups of 4 consecutive floats, keep first-max, zero others.
// 4096 x 8192 fp32 -> 8,388,608 groups (float4s).
// Each thread handles GPT=4 groups with front-batched loads (MLP_p1=4),
// strided by total-thread-count so every batched load stays coalesced.

#define GPT 4

__global__ void lwta_kernel(const float4* __restrict__ in,
                            float4* __restrict__ out,
                            int n_groups) {
    int tid = blockIdx.x * blockDim.x + threadIdx.x;
    int stride = gridDim.x * blockDim.x;   // == n_groups / GPT (exact launch)

    // Front-batch all loads: 4 independent LDG.128 in flight.
    float4 v[GPT];
#pragma unroll
    for (int j = 0; j < GPT; j++) {
        int idx = tid + j * stride;
        v[j] = in[idx];
    }

#pragma unroll
    for (int j = 0; j < GPT; j++) {
        float4 a = v[j];
        float m = fmaxf(fmaxf(a.x, a.y), fmaxf(a.z, a.w));
        // first-max winner (jnp.argmax tie-break)
        int w = (a.x == m) ? 0 : (a.y == m) ? 1 : (a.z == m) ? 2 : 3;
        float4 o;
        o.x = (w == 0) ? a.x : 0.0f;
        o.y = (w == 1) ? a.y : 0.0f;
        o.z = (w == 2) ? a.z : 0.0f;
        o.w = (w == 3) ? a.w : 0.0f;
        out[tid + j * stride] = o;
    }
}

extern "C" void kernel_launch(void* const* d_in, const int* in_sizes, int n_in,
                              void* d_out, int out_size) {
    const float4* in = (const float4*)d_in[0];
    float4* out = (float4*)d_out;
    int n_groups = in_sizes[0] / 4;        // 8,388,608

    const int threads = 256;
    int total_threads = n_groups / GPT;    // 2,097,152 (exact: 8192*256*4 groups)
    int blocks = total_threads / threads;  // 8192
    lwta_kernel<<<blocks, threads>>>(in, out, n_groups);
}